// round 2
// baseline (speedup 1.0000x reference)
#include <cuda_runtime.h>
#include <math.h>

// Problem dims (fixed by the reference)
#define TT  16384   // tokens = B*S
#define HH  1024    // hidden
#define EE  8       // routed experts
#define KK  2       // top-k
#define DEE 128     // routed expert hidden
#define DSS 512     // shared expert hidden

// ---------------- device scratch (static __device__ globals per harness rules) ----------
__device__ int   g_cnt[EE];
__device__ int   g_off[EE + 1];
__device__ int   g_pos[EE];
__device__ int   g_top_idx[TT * KK];
__device__ float g_top_w[TT * KK];
__device__ int   g_tok[TT * KK];      // per compact slot: source token
__device__ float g_wt[TT * KK];       // per compact slot: combine weight
__device__ int   g_slot[TT * KK];     // per (token,k): compact slot id
__device__ float g_h1[TT * KK * DEE];           // routed fc1 activations (16.8 MB)
__device__ float g_hs[TT * DSS];                // shared fc1 activations (33.5 MB)
__device__ float g_y2[TT * KK * HH];            // routed fc2 outputs      (134 MB)

// ---------------- small kernels ----------------
__global__ void k_zero_cnt() {
    if (threadIdx.x < EE) g_cnt[threadIdx.x] = 0;
}

// One warp per token: logits(8) -> softmax -> top2 -> normalized weights + counts
__global__ void k_gate(const float* __restrict__ x, const float* __restrict__ Wg) {
    int warp = (blockIdx.x * blockDim.x + threadIdx.x) >> 5;
    int lane = threadIdx.x & 31;
    if (warp >= TT) return;
    const float* xr = x + (size_t)warp * HH;
    float acc[EE];
#pragma unroll
    for (int e = 0; e < EE; e++) acc[e] = 0.f;
    for (int j = lane; j < HH; j += 32) {
        float xv = xr[j];
#pragma unroll
        for (int e = 0; e < EE; e++) acc[e] += xv * Wg[e * HH + j];
    }
#pragma unroll
    for (int e = 0; e < EE; e++) {
#pragma unroll
        for (int off = 16; off; off >>= 1)
            acc[e] += __shfl_xor_sync(0xFFFFFFFFu, acc[e], off);
    }
    if (lane == 0) {
        float mx = acc[0];
#pragma unroll
        for (int e = 1; e < EE; e++) mx = fmaxf(mx, acc[e]);
        float p[EE], s = 0.f;
#pragma unroll
        for (int e = 0; e < EE; e++) { p[e] = expf(acc[e] - mx); s += p[e]; }
        // top-2 (strict > keeps smallest index on ties, matching jax top_k)
        int i0 = 0;
#pragma unroll
        for (int e = 1; e < EE; e++) if (p[e] > p[i0]) i0 = e;
        int i1 = (i0 == 0) ? 1 : 0;
#pragma unroll
        for (int e = 0; e < EE; e++) if (e != i0 && p[e] > p[i1]) i1 = e;
        float sc0 = p[i0] / s, sc1 = p[i1] / s;
        float inv = 1.f / (sc0 + sc1 + 1e-20f);
        g_top_idx[warp * 2 + 0] = i0;
        g_top_idx[warp * 2 + 1] = i1;
        g_top_w[warp * 2 + 0] = sc0 * inv;
        g_top_w[warp * 2 + 1] = sc1 * inv;
        atomicAdd(&g_cnt[i0], 1);
        atomicAdd(&g_cnt[i1], 1);
    }
}

__global__ void k_prefix() {
    if (threadIdx.x == 0) {
        int acc = 0;
#pragma unroll
        for (int e = 0; e < EE; e++) { g_off[e] = acc; acc += g_cnt[e]; }
        g_off[EE] = acc;
    }
    if (threadIdx.x < EE) g_pos[threadIdx.x] = 0;
}

__global__ void k_scatter() {
    int t = blockIdx.x * blockDim.x + threadIdx.x;
    if (t >= TT) return;
#pragma unroll
    for (int k = 0; k < KK; k++) {
        int e = g_top_idx[t * 2 + k];
        int s = g_off[e] + atomicAdd(&g_pos[e], 1);
        g_tok[s] = t;
        g_wt[s] = g_top_w[t * 2 + k];
        g_slot[t * 2 + k] = s;
    }
}

// ---------------- tiled fp32 GEMM core: C[M,N] = A[M,K] * B[N,K]^T ----------------
#define BM 128
#define BN 128
#define BK 16
#define TM 8
#define TN 8
#define NTH 256

template <bool GATHER, bool RELU, bool HASBIAS, bool SCALE>
__device__ __forceinline__ void gemm_tile(
    const float* __restrict__ A, int lda,
    const float* __restrict__ B, int ldb,
    const float* __restrict__ bias,
    float* __restrict__ C, int ldc,
    int Kd, int m0, int m_end, int n0,
    const int* __restrict__ gidx,
    const float* __restrict__ rowsc)
{
    __shared__ float As[BK][BM + 4];
    __shared__ float Bs[BK][BN + 4];
    const int tid = threadIdx.x;
    const int tx = tid & 15;
    const int ty = tid >> 4;

    float acc[TM][TN];
#pragma unroll
    for (int i = 0; i < TM; i++)
#pragma unroll
        for (int j = 0; j < TN; j++) acc[i][j] = 0.f;

    // Each thread stages 2 float4 of A and 2 float4 of B per k-step
    const float* aptr[2]; bool aval[2]; int arow[2], acol[2];
    const float* bptr[2]; int brow[2], bcol[2];
#pragma unroll
    for (int i = 0; i < 2; i++) {
        int li = tid * 2 + i;
        int r = li >> 2;            // 0..127
        int c = (li & 3) << 2;      // 0,4,8,12
        arow[i] = r; acol[i] = c;
        int gm = m0 + r;
        aval[i] = gm < m_end;
        int src = 0;
        if (aval[i]) src = GATHER ? gidx[gm] : gm;
        aptr[i] = A + (size_t)src * lda + c;
        brow[i] = r; bcol[i] = c;
        bptr[i] = B + (size_t)(n0 + r) * ldb + c;
    }

    for (int k0 = 0; k0 < Kd; k0 += BK) {
        __syncthreads();
#pragma unroll
        for (int i = 0; i < 2; i++) {
            float4 av = aval[i] ? *(const float4*)(aptr[i] + k0)
                                : make_float4(0.f, 0.f, 0.f, 0.f);
            As[acol[i] + 0][arow[i]] = av.x;
            As[acol[i] + 1][arow[i]] = av.y;
            As[acol[i] + 2][arow[i]] = av.z;
            As[acol[i] + 3][arow[i]] = av.w;
            float4 bv = *(const float4*)(bptr[i] + k0);
            Bs[bcol[i] + 0][brow[i]] = bv.x;
            Bs[bcol[i] + 1][brow[i]] = bv.y;
            Bs[bcol[i] + 2][brow[i]] = bv.z;
            Bs[bcol[i] + 3][brow[i]] = bv.w;
        }
        __syncthreads();
#pragma unroll
        for (int k = 0; k < BK; k++) {
            float ra[TM], rb[TN];
#pragma unroll
            for (int i = 0; i < TM; i++) ra[i] = As[k][ty * TM + i];
#pragma unroll
            for (int j = 0; j < TN; j++) rb[j] = Bs[k][tx * TN + j];
#pragma unroll
            for (int i = 0; i < TM; i++)
#pragma unroll
                for (int j = 0; j < TN; j++)
                    acc[i][j] += ra[i] * rb[j];
        }
    }

    // epilogue: (+bias) (*rowscale) (relu) -> C
#pragma unroll
    for (int i = 0; i < TM; i++) {
        int gm = m0 + ty * TM + i;
        if (gm >= m_end) break;
        float sc = SCALE ? rowsc[gm] : 1.f;
        float v[TN];
#pragma unroll
        for (int j = 0; j < TN; j++) {
            float t = acc[i][j];
            if (HASBIAS) t += bias[n0 + tx * TN + j];
            if (SCALE)   t *= sc;
            if (RELU)    t = fmaxf(t, 0.f);
            v[j] = t;
        }
        float* cp = C + (size_t)gm * ldc + n0 + tx * TN;
        *(float4*)cp       = make_float4(v[0], v[1], v[2], v[3]);
        *(float4*)(cp + 4) = make_float4(v[4], v[5], v[6], v[7]);
    }
}

// ---------------- GEMM wrappers ----------------
__global__ __launch_bounds__(NTH) void k_shared_fc1(
    const float* __restrict__ x, const float* __restrict__ Ws1,
    const float* __restrict__ bs1)
{
    gemm_tile<false, true, true, false>(
        x, HH, Ws1, HH, bs1, g_hs, DSS, HH,
        blockIdx.x * BM, TT, blockIdx.y * BN, nullptr, nullptr);
}

__global__ __launch_bounds__(NTH) void k_shared_fc2(
    const float* __restrict__ Ws2, const float* __restrict__ bs2,
    float* __restrict__ out)
{
    gemm_tile<false, false, true, false>(
        g_hs, DSS, Ws2, DSS, bs2, out, HH, DSS,
        blockIdx.x * BM, TT, blockIdx.y * BN, nullptr, nullptr);
}

__global__ __launch_bounds__(NTH) void k_routed_fc1(
    const float* __restrict__ x, const float* __restrict__ W1,
    const float* __restrict__ b1)
{
    int e = blockIdx.z;
    int s0 = g_off[e], s1 = g_off[e + 1];
    int m0 = s0 + blockIdx.x * BM;
    if (m0 >= s1) return;
    gemm_tile<true, true, true, false>(
        x, HH, W1 + (size_t)e * DEE * HH, HH, b1 + e * DEE,
        g_h1, DEE, HH, m0, s1, 0, g_tok, nullptr);
}

__global__ __launch_bounds__(NTH) void k_routed_fc2(
    const float* __restrict__ W2, const float* __restrict__ b2)
{
    int e = blockIdx.z;
    int s0 = g_off[e], s1 = g_off[e + 1];
    int m0 = s0 + blockIdx.x * BM;
    if (m0 >= s1) return;
    // per-slot contribution = wt * (h1 @ W2[e]^T + b2[e])
    gemm_tile<false, false, true, true>(
        g_h1, DEE, W2 + (size_t)e * HH * DEE, DEE, b2 + (size_t)e * HH,
        g_y2, HH, DEE, m0, s1, blockIdx.y * BN, nullptr, g_wt);
}

// out[t] = shared(t) + y2[slot0(t)] + y2[slot1(t)]   (deterministic combine)
__global__ void k_combine(float* __restrict__ out) {
    const int n4 = HH / 4;
    int i = blockIdx.x * blockDim.x + threadIdx.x;
    if (i >= TT * n4) return;
    int t = i / n4;
    int c = i - t * n4;
    int s0 = g_slot[t * 2 + 0];
    int s1 = g_slot[t * 2 + 1];
    const float4* y = (const float4*)g_y2;
    float4 o = ((const float4*)out)[i];
    float4 a = y[(size_t)s0 * n4 + c];
    float4 b = y[(size_t)s1 * n4 + c];
    o.x += a.x + b.x;
    o.y += a.y + b.y;
    o.z += a.z + b.z;
    o.w += a.w + b.w;
    ((float4*)out)[i] = o;
}

// ---------------- launch ----------------
extern "C" void kernel_launch(void* const* d_in, const int* in_sizes, int n_in,
                              void* d_out, int out_size) {
    const float* x   = (const float*)d_in[0];
    const float* Wg  = (const float*)d_in[1];
    const float* W1  = (const float*)d_in[2];
    const float* b1  = (const float*)d_in[3];
    const float* W2  = (const float*)d_in[4];
    const float* b2  = (const float*)d_in[5];
    const float* Ws1 = (const float*)d_in[6];
    const float* bs1 = (const float*)d_in[7];
    const float* Ws2 = (const float*)d_in[8];
    const float* bs2 = (const float*)d_in[9];
    float* out = (float*)d_out;

    k_zero_cnt<<<1, 32>>>();
    k_gate<<<TT / 8, 256>>>(x, Wg);                       // 8 warps/block, 1 token/warp
    k_prefix<<<1, 32>>>();
    k_scatter<<<TT / 256, 256>>>();

    k_shared_fc1<<<dim3(TT / BM, DSS / BN), NTH>>>(x, Ws1, bs1);
    k_shared_fc2<<<dim3(TT / BM, HH / BN),  NTH>>>(Ws2, bs2, out);   // initializes out

    k_routed_fc1<<<dim3(TT / BM, 1, EE),       NTH>>>(x, W1, b1);    // worst-case grid, blocks self-select
    k_routed_fc2<<<dim3(TT / BM, HH / BN, EE), NTH>>>(W2, b2);

    k_combine<<<(TT * (HH / 4) + 255) / 256, 256>>>(out);
}